// round 1
// baseline (speedup 1.0000x reference)
#include <cuda_runtime.h>
#include <cuda_bf16.h>
#include <math.h>

#define N_NODES   50000
#define N_HEDGES  100000
#define E_INC     800000
#define N_GRAPHS  512
#define IN_DIM    92
#define H_DIM     64
#define HOUT      128
#define HEDGE_DIM 35
#define Z_DIM     163   // 64 + 35 + 64
#define N_LAYERS  3

typedef unsigned long long ull;

// ---------------- scratch (device globals; no allocation allowed) ----------
__device__ float g_hA[N_NODES * H_DIM];
__device__ float g_hB[N_NODES * H_DIM];
__device__ float g_hxs[N_HEDGES * H_DIM];
__device__ float g_nodeagg[N_NODES * H_DIM];
__device__ float g_attragg[N_NODES * HEDGE_DIM];

__device__ int g_hcnt[N_HEDGES];
__device__ int g_ncnt[N_NODES];
__device__ int g_hoff[N_HEDGES + 1];
__device__ int g_noff[N_NODES + 1];
__device__ int g_hfill[N_HEDGES];
__device__ int g_nfill[N_NODES];
__device__ int g_csr_h[E_INC];   // node ids grouped by hedge
__device__ int g_csr_n[E_INC];   // hedge ids grouped by node
__device__ int g_part[256];

// ---------------- helpers ----------------
__device__ __forceinline__ float softplusf(float x) {
    return fmaxf(x, 0.f) + log1pf(expf(-fabsf(x)));
}
__device__ __forceinline__ float sigmoidf(float x) {
    return 1.f / (1.f + expf(-x));
}
__device__ __forceinline__ ull packf2(float x, float y) {
    ull r;
    asm("mov.b64 %0, {%1, %2};" : "=l"(r)
        : "r"(__float_as_uint(x)), "r"(__float_as_uint(y)));
    return r;
}
__device__ __forceinline__ ull packdup(float x) { return packf2(x, x); }
__device__ __forceinline__ float2 unpk(ull v) {
    unsigned a, b;
    asm("mov.b64 {%0, %1}, %2;" : "=r"(a), "=r"(b) : "l"(v));
    return make_float2(__uint_as_float(a), __uint_as_float(b));
}
__device__ __forceinline__ void fma2(ull &c, ull a, ull b) {
    asm("fma.rn.f32x2 %0, %1, %2, %0;" : "+l"(c) : "l"(a), "l"(b));
}

// ---------------- CSR construction ----------------
__global__ void count_kernel(const int *__restrict__ node_idx,
                             const int *__restrict__ hedge_idx) {
    int e = blockIdx.x * blockDim.x + threadIdx.x;
    if (e < E_INC) {
        atomicAdd(&g_hcnt[hedge_idx[e]], 1);
        atomicAdd(&g_ncnt[node_idx[e]], 1);
    }
}

__global__ void scan_partial(const int *__restrict__ cnt, int *__restrict__ partial, int n) {
    __shared__ int s[1024];
    int i = blockIdx.x * 1024 + threadIdx.x;
    s[threadIdx.x] = (i < n) ? cnt[i] : 0;
    __syncthreads();
    for (int d = 512; d > 0; d >>= 1) {
        if (threadIdx.x < d) s[threadIdx.x] += s[threadIdx.x + d];
        __syncthreads();
    }
    if (threadIdx.x == 0) partial[blockIdx.x] = s[0];
}

__global__ void scan_excl(int *partial, int nb) {
    if (threadIdx.x == 0) {
        int run = 0;
        for (int i = 0; i < nb; i++) { int t = partial[i]; partial[i] = run; run += t; }
    }
}

__global__ void scan_final(const int *__restrict__ cnt, const int *__restrict__ partial,
                           int *__restrict__ off, int *__restrict__ fill, int n) {
    __shared__ int s[1024];
    int t = threadIdx.x;
    int i = blockIdx.x * 1024 + t;
    int v = (i < n) ? cnt[i] : 0;
    s[t] = v;
    __syncthreads();
    for (int d = 1; d < 1024; d <<= 1) {
        int x = (t >= d) ? s[t - d] : 0;
        __syncthreads();
        s[t] += x;
        __syncthreads();
    }
    int excl = s[t] - v + partial[blockIdx.x];
    if (i < n) {
        off[i] = excl;
        fill[i] = excl;
        if (i == n - 1) off[n] = excl + v;
    }
}

__global__ void fill_kernel(const int *__restrict__ node_idx,
                            const int *__restrict__ hedge_idx) {
    int e = blockIdx.x * blockDim.x + threadIdx.x;
    if (e < E_INC) {
        int nd = node_idx[e], he = hedge_idx[e];
        int p = atomicAdd(&g_hfill[he], 1);
        g_csr_h[p] = nd;
        int p2 = atomicAdd(&g_nfill[nd], 1);
        g_csr_n[p2] = he;
    }
}

// ---------------- embed: h = x @ W_embed + b ----------------
__global__ void __launch_bounds__(256) embed_kernel(
    const float *__restrict__ x, const float *__restrict__ W,
    const float *__restrict__ b, float *__restrict__ h) {
    __shared__ float W_s[IN_DIM * H_DIM];   // 23.5 KB
    __shared__ float x_s[4][IN_DIM];
    for (int i = threadIdx.x; i < IN_DIM * H_DIM; i += 256) W_s[i] = W[i];
    int col = threadIdx.x & 63, sub = threadIdx.x >> 6;
    float bv = b[col];
    for (int nb = blockIdx.x * 4; nb < N_NODES; nb += gridDim.x * 4) {
        __syncthreads();
        for (int i = threadIdx.x; i < 4 * IN_DIM; i += 256) {
            int n = i / IN_DIM, k = i - n * IN_DIM;
            int node = nb + n;
            x_s[n][k] = (node < N_NODES) ? x[node * IN_DIM + k] : 0.f;
        }
        __syncthreads();
        int node = nb + sub;
        if (node < N_NODES) {
            float acc = bv;
#pragma unroll
            for (int k = 0; k < IN_DIM; k++) acc += x_s[sub][k] * W_s[k * H_DIM + col];
            h[node * H_DIM + col] = acc;
        }
    }
}

// ---------------- gather aggregations (warp per segment) ----------------
__global__ void __launch_bounds__(256) hedge_agg_kernel(const float *__restrict__ hin) {
    int he = blockIdx.x * 8 + (threadIdx.x >> 5);
    if (he >= N_HEDGES) return;
    int lane = threadIdx.x & 31;
    int beg = g_hoff[he], end = g_hoff[he + 1];
    float2 acc = make_float2(0.f, 0.f);
    int m = beg;
    for (; m + 4 <= end; m += 4) {
        int n0 = g_csr_h[m], n1 = g_csr_h[m + 1], n2 = g_csr_h[m + 2], n3 = g_csr_h[m + 3];
        float2 v0 = *(const float2 *)(hin + n0 * H_DIM + lane * 2);
        float2 v1 = *(const float2 *)(hin + n1 * H_DIM + lane * 2);
        float2 v2 = *(const float2 *)(hin + n2 * H_DIM + lane * 2);
        float2 v3 = *(const float2 *)(hin + n3 * H_DIM + lane * 2);
        acc.x += v0.x + v1.x + v2.x + v3.x;
        acc.y += v0.y + v1.y + v2.y + v3.y;
    }
    for (; m < end; m++) {
        int nd = g_csr_h[m];
        float2 v = *(const float2 *)(hin + nd * H_DIM + lane * 2);
        acc.x += v.x; acc.y += v.y;
    }
    int deg = end - beg;
    float inv = 1.f / (float)(deg > 0 ? deg : 1);
    *(float2 *)(g_hxs + he * H_DIM + lane * 2) = make_float2(acc.x * inv, acc.y * inv);
}

__global__ void __launch_bounds__(256) node_agg_kernel() {
    int nd = blockIdx.x * 8 + (threadIdx.x >> 5);
    if (nd >= N_NODES) return;
    int lane = threadIdx.x & 31;
    int beg = g_noff[nd], end = g_noff[nd + 1];
    float2 acc = make_float2(0.f, 0.f);
    int m = beg;
    for (; m + 4 <= end; m += 4) {
        int h0 = g_csr_n[m], h1 = g_csr_n[m + 1], h2 = g_csr_n[m + 2], h3 = g_csr_n[m + 3];
        float2 v0 = *(const float2 *)(g_hxs + h0 * H_DIM + lane * 2);
        float2 v1 = *(const float2 *)(g_hxs + h1 * H_DIM + lane * 2);
        float2 v2 = *(const float2 *)(g_hxs + h2 * H_DIM + lane * 2);
        float2 v3 = *(const float2 *)(g_hxs + h3 * H_DIM + lane * 2);
        acc.x += v0.x + v1.x + v2.x + v3.x;
        acc.y += v0.y + v1.y + v2.y + v3.y;
    }
    for (; m < end; m++) {
        int he = g_csr_n[m];
        float2 v = *(const float2 *)(g_hxs + he * H_DIM + lane * 2);
        acc.x += v.x; acc.y += v.y;
    }
    int deg = end - beg;
    float inv = 1.f / (float)(deg > 0 ? deg : 1);
    *(float2 *)(g_nodeagg + nd * H_DIM + lane * 2) = make_float2(acc.x * inv, acc.y * inv);
}

// layer-invariant: per-node mean of incident hedge_attr rows
__global__ void __launch_bounds__(256) attr_agg_kernel(const float *__restrict__ hedge_attr) {
    int nd = blockIdx.x * 8 + (threadIdx.x >> 5);
    if (nd >= N_NODES) return;
    int lane = threadIdx.x & 31;
    int beg = g_noff[nd], end = g_noff[nd + 1];
    float a0 = 0.f, a1 = 0.f;
    for (int m = beg; m < end; m++) {
        int he = g_csr_n[m];
        const float *r = hedge_attr + he * HEDGE_DIM;
        a0 += r[lane];
        if (lane < 3) a1 += r[32 + lane];
    }
    int deg = end - beg;
    float inv = 1.f / (float)(deg > 0 ? deg : 1);
    g_attragg[nd * HEDGE_DIM + lane] = a0 * inv;
    if (lane < 3) g_attragg[nd * HEDGE_DIM + 32 + lane] = a1 * inv;
}

// ---------------- per-layer dual GEMM + gated activation + residual -------
// 64 nodes / block, 128 threads. Each thread: 2 nodes x 32 combined cols.
// Combined cols 0..63 = Wf (z_f), 64..127 = Wc (z_c). f32x2 packed FMA.
#define GEMM_SMEM (64 * Z_DIM * 4 + 32 * 128 * 4)   // 58112 B
__global__ void __launch_bounds__(128) gemm_act_kernel(
    const float *__restrict__ h_in,
    const float *__restrict__ Wf, const float *__restrict__ bf,
    const float *__restrict__ Wc, const float *__restrict__ bc,
    float *__restrict__ h_out) {
    extern __shared__ float sm[];
    float *z_s = sm;                      // [64][Z_DIM]
    float *W_s = sm + 64 * Z_DIM;         // [32][128]
    const int tid = threadIdx.x;
    const int nbase = blockIdx.x * 64;

    // stage z for 64 nodes: [h (0 if deg==0) | attragg | nodeagg]
    for (int idx = tid; idx < 64 * Z_DIM; idx += 128) {
        int n = idx / Z_DIM, k = idx - n * Z_DIM;
        int node = nbase + n;
        float v = 0.f;
        if (node < N_NODES) {
            if (k < 64)      v = (g_noff[node + 1] > g_noff[node]) ? h_in[node * H_DIM + k] : 0.f;
            else if (k < 99) v = g_attragg[node * HEDGE_DIM + (k - 64)];
            else             v = g_nodeagg[node * H_DIM + (k - 99)];
        }
        z_s[n * Z_DIM + k] = v;
    }

    const int lane = tid & 31, w = tid >> 5;
    const int q = lane & 3, nsub = lane >> 2;
    const int nl0 = w * 8 + nsub;
    const int nl1 = nl0 + 32;

    ull acc0[16], acc1[16];
#pragma unroll
    for (int i = 0; i < 16; i++) { acc0[i] = 0ull; acc1[i] = 0ull; }

    for (int kb = 0; kb < Z_DIM; kb += 32) {
        int kc = (Z_DIM - kb < 32) ? (Z_DIM - kb) : 32;
        __syncthreads();
        for (int idx = tid; idx < kc * 128; idx += 128) {
            int k = idx >> 7, c = idx & 127;
            W_s[k * 128 + c] = (c < 64) ? Wf[(kb + k) * 64 + c]
                                        : Wc[(kb + k) * 64 + (c - 64)];
        }
        __syncthreads();
        for (int k = 0; k < kc; k++) {
            ull a0 = packdup(z_s[nl0 * Z_DIM + kb + k]);
            ull a1 = packdup(z_s[nl1 * Z_DIM + kb + k]);
            const float4 *wr = (const float4 *)(W_s + k * 128 + q * 32);
#pragma unroll
            for (int i = 0; i < 8; i++) {
                float4 wv = wr[i];
                ull b0 = packf2(wv.x, wv.y);
                ull b1 = packf2(wv.z, wv.w);
                fma2(acc0[2 * i],     a0, b0);
                fma2(acc0[2 * i + 1], a0, b1);
                fma2(acc1[2 * i],     a1, b0);
                fma2(acc1[2 * i + 1], a1, b1);
            }
        }
    }

    // epilogue: bias, pair f(q<2) with c(q>=2) via shfl_xor(2), activate, residual
    const float *bias = (q < 2) ? bf : bc;
    const int halfbase = (q & 1) * 32;
#pragma unroll
    for (int which = 0; which < 2; which++) {
        ull *acc = which ? acc1 : acc0;
        int node = nbase + (which ? nl1 : nl0);
#pragma unroll
        for (int i = 0; i < 16; i++) {
            float2 y = unpk(acc[i]);
            int col = halfbase + 2 * i;
            y.x += bias[col];
            y.y += bias[col + 1];
            float ox = __shfl_xor_sync(0xffffffffu, y.x, 2);
            float oy = __shfl_xor_sync(0xffffffffu, y.y, 2);
            if (q < 2 && node < N_NODES) {
                int base = node * H_DIM + col;
                float o0 = sigmoidf(y.x) * softplusf(ox);
                float o1 = sigmoidf(y.y) * softplusf(oy);
                h_out[base]     = softplusf(o0 + h_in[base]);
                h_out[base + 1] = softplusf(o1 + h_in[base + 1]);
            }
        }
    }
}

// ---------------- pooling + readout MLP (block per graph) ----------------
__global__ void __launch_bounds__(128) pool_mlp_kernel(
    const float *__restrict__ h, const int *__restrict__ batch,
    const float *__restrict__ Wp, const float *__restrict__ bp,
    const float *__restrict__ Wo, const float *__restrict__ bo,
    float *__restrict__ out) {
    int g = blockIdx.x;
    int tid = threadIdx.x;
    __shared__ int s_lo, s_hi;
    if (tid == 0) {
        int lo = 0, hi = N_NODES;
        while (lo < hi) { int mid = (lo + hi) >> 1; if (batch[mid] < g) lo = mid + 1; else hi = mid; }
        s_lo = lo;
    }
    if (tid == 1) {
        int lo = 0, hi = N_NODES;
        while (lo < hi) { int mid = (lo + hi) >> 1; if (batch[mid] < g + 1) lo = mid + 1; else hi = mid; }
        s_hi = lo;
    }
    __syncthreads();
    int lo = s_lo, hi = s_hi;
    int col = tid & 63, sub = tid >> 6;
    float acc = 0.f;
    for (int i = lo + sub; i < hi; i += 2) acc += h[i * H_DIM + col];
    __shared__ float gs[2][H_DIM];
    gs[sub][col] = acc;
    __syncthreads();
    __shared__ float gvec[H_DIM];
    if (tid < 64) {
        int cnt = hi - lo;
        gvec[tid] = (gs[0][tid] + gs[1][tid]) / (float)(cnt > 0 ? cnt : 1);
    }
    __syncthreads();
    // proj: each thread computes one of 128 outputs
    float p = bp[tid];
#pragma unroll
    for (int k = 0; k < H_DIM; k++) p += gvec[k] * Wp[k * HOUT + tid];
    p = softplusf(p);
    float r = p * Wo[tid];
    // block reduce 128 -> 1
#pragma unroll
    for (int off = 16; off > 0; off >>= 1) r += __shfl_down_sync(0xffffffffu, r, off);
    __shared__ float red[4];
    if ((tid & 31) == 0) red[tid >> 5] = r;
    __syncthreads();
    if (tid == 0) out[g] = red[0] + red[1] + red[2] + red[3] + bo[0];
}

// ---------------- launch ----------------
extern "C" void kernel_launch(void *const *d_in, const int *in_sizes, int n_in,
                              void *d_out, int out_size) {
    const float *x          = (const float *)d_in[0];
    const float *hedge_attr = (const float *)d_in[1];
    const int   *node_idx   = (const int *)d_in[2];
    const int   *hedge_idx  = (const int *)d_in[3];
    const int   *batch      = (const int *)d_in[4];
    const float *W_embed    = (const float *)d_in[5];
    const float *b_embed    = (const float *)d_in[6];
    const float *Wf         = (const float *)d_in[7];
    const float *bf         = (const float *)d_in[8];
    const float *Wc         = (const float *)d_in[9];
    const float *bc         = (const float *)d_in[10];
    const float *Wp         = (const float *)d_in[11];
    const float *bp         = (const float *)d_in[12];
    const float *Wo         = (const float *)d_in[13];
    const float *bo         = (const float *)d_in[14];
    float *out = (float *)d_out;

    void *p_hcnt, *p_ncnt, *p_part, *p_hoff, *p_hfill, *p_noff, *p_nfill, *p_hA, *p_hB;
    cudaGetSymbolAddress(&p_hcnt, g_hcnt);
    cudaGetSymbolAddress(&p_ncnt, g_ncnt);
    cudaGetSymbolAddress(&p_part, g_part);
    cudaGetSymbolAddress(&p_hoff, g_hoff);
    cudaGetSymbolAddress(&p_hfill, g_hfill);
    cudaGetSymbolAddress(&p_noff, g_noff);
    cudaGetSymbolAddress(&p_nfill, g_nfill);
    cudaGetSymbolAddress(&p_hA, g_hA);
    cudaGetSymbolAddress(&p_hB, g_hB);
    float *hA = (float *)p_hA;
    float *hB = (float *)p_hB;

    cudaFuncSetAttribute(gemm_act_kernel,
                         cudaFuncAttributeMaxDynamicSharedMemorySize, GEMM_SMEM);

    // CSR build
    cudaMemsetAsync(p_hcnt, 0, sizeof(int) * N_HEDGES);
    cudaMemsetAsync(p_ncnt, 0, sizeof(int) * N_NODES);
    count_kernel<<<(E_INC + 255) / 256, 256>>>(node_idx, hedge_idx);
    int nbh = (N_HEDGES + 1023) / 1024;
    int nbn = (N_NODES + 1023) / 1024;
    scan_partial<<<nbh, 1024>>>((int *)p_hcnt, (int *)p_part, N_HEDGES);
    scan_excl<<<1, 32>>>((int *)p_part, nbh);
    scan_final<<<nbh, 1024>>>((int *)p_hcnt, (int *)p_part, (int *)p_hoff, (int *)p_hfill, N_HEDGES);
    scan_partial<<<nbn, 1024>>>((int *)p_ncnt, (int *)p_part, N_NODES);
    scan_excl<<<1, 32>>>((int *)p_part, nbn);
    scan_final<<<nbn, 1024>>>((int *)p_ncnt, (int *)p_part, (int *)p_noff, (int *)p_nfill, N_NODES);
    fill_kernel<<<(E_INC + 255) / 256, 256>>>(node_idx, hedge_idx);

    // embed
    embed_kernel<<<1184, 256>>>(x, W_embed, b_embed, hA);

    // layer-invariant hedge_attr aggregation
    attr_agg_kernel<<<(N_NODES + 7) / 8, 256>>>(hedge_attr);

    // 3 CHGConv layers (ping-pong hA/hB)
    float *hcur = hA, *hnext = hB;
    for (int l = 0; l < N_LAYERS; l++) {
        hedge_agg_kernel<<<(N_HEDGES + 7) / 8, 256>>>(hcur);
        node_agg_kernel<<<(N_NODES + 7) / 8, 256>>>();
        gemm_act_kernel<<<(N_NODES + 63) / 64, 128, GEMM_SMEM>>>(
            hcur,
            Wf + (size_t)l * Z_DIM * H_DIM, bf + (size_t)l * H_DIM,
            Wc + (size_t)l * Z_DIM * H_DIM, bc + (size_t)l * H_DIM,
            hnext);
        float *t = hcur; hcur = hnext; hnext = t;
    }

    // pooling + readout
    pool_mlp_kernel<<<N_GRAPHS, 128>>>(hcur, batch, Wp, bp, Wo, bo, out);
}

// round 6
// speedup vs baseline: 1.0141x; 1.0141x over previous
#include <cuda_runtime.h>
#include <cuda_bf16.h>
#include <math.h>

#define N_NODES   50000
#define N_HEDGES  100000
#define E_INC     800000
#define N_GRAPHS  512
#define IN_DIM    92
#define H_DIM     64
#define HOUT      128
#define HEDGE_DIM 35
#define Z_DIM     163   // 64 + 35 + 64
#define N_LAYERS  3

#define NBH 98            // ceil(100000/1024)
#define NBN 49            // ceil(50000/1024)
#define NBT (NBH + NBN)   // 147

typedef unsigned long long ull;

// ---------------- scratch (device globals; no allocation allowed) ----------
__device__ float g_hA[N_NODES * H_DIM];
__device__ float g_hB[N_NODES * H_DIM];
__device__ float g_hxs[N_HEDGES * H_DIM];
__device__ float g_attragg[N_NODES * HEDGE_DIM];

__device__ int g_hcnt[N_HEDGES];
__device__ int g_ncnt[N_NODES];
__device__ int g_hoff[N_HEDGES + 1];
__device__ int g_noff[N_NODES + 1];
__device__ int g_hfill[N_HEDGES];
__device__ int g_nfill[N_NODES];
__device__ int g_csr_h[E_INC];   // node ids grouped by hedge
__device__ int g_csr_n[E_INC];   // hedge ids grouped by node
__device__ int g_part[256];

// ---------------- helpers ----------------
__device__ __forceinline__ float softplusf(float x) {
    return fmaxf(x, 0.f) + log1pf(expf(-fabsf(x)));
}
__device__ __forceinline__ float sigmoidf(float x) {
    return 1.f / (1.f + expf(-x));
}
__device__ __forceinline__ ull packdup(float x) {
    ull r;
    asm("mov.b64 %0, {%1, %2};" : "=l"(r)
        : "r"(__float_as_uint(x)), "r"(__float_as_uint(x)));
    return r;
}
__device__ __forceinline__ float2 unpk(ull v) {
    unsigned a, b;
    asm("mov.b64 {%0, %1}, %2;" : "=r"(a), "=r"(b) : "l"(v));
    return make_float2(__uint_as_float(a), __uint_as_float(b));
}
__device__ __forceinline__ void fma2(ull &c, ull a, ull b) {
    asm("fma.rn.f32x2 %0, %1, %2, %0;" : "+l"(c) : "l"(a), "l"(b));
}

// ---------------- CSR construction ----------------
// counts are zeroed by the TAIL of fill_kernel (previous replay / correctness
// run), and are zero at module load. No memsets needed.
__global__ void count_kernel(const int *__restrict__ node_idx,
                             const int *__restrict__ hedge_idx) {
    int e = blockIdx.x * blockDim.x + threadIdx.x;
    if (e < E_INC) {
        atomicAdd(&g_hcnt[hedge_idx[e]], 1);
        atomicAdd(&g_ncnt[node_idx[e]], 1);
    }
}

// one launch: per-chunk sums for BOTH count arrays (blocks 0..NBH-1 = hedges,
// NBH..NBT-1 = nodes)
__global__ void __launch_bounds__(1024) scan_partial_both() {
    __shared__ int s[1024];
    int b = blockIdx.x;
    const int *cnt = (b < NBH) ? g_hcnt : g_ncnt;
    int n = (b < NBH) ? N_HEDGES : N_NODES;
    int chunk = (b < NBH) ? b : b - NBH;
    int i = chunk * 1024 + threadIdx.x;
    s[threadIdx.x] = (i < n) ? cnt[i] : 0;
    __syncthreads();
    for (int d = 512; d > 0; d >>= 1) {
        if (threadIdx.x < d) s[threadIdx.x] += s[threadIdx.x + d];
        __syncthreads();
    }
    if (threadIdx.x == 0) g_part[b] = s[0];
}

// one launch: each block computes its own base = sum of partials in its
// range, then the in-chunk exclusive scan. Writes off + fill.
__global__ void __launch_bounds__(1024) scan_final_both() {
    __shared__ int s[1024];
    __shared__ int red[32];
    __shared__ int sbase;
    int b = blockIdx.x;
    bool isH = b < NBH;
    const int *cnt = isH ? g_hcnt : g_ncnt;
    int *off  = isH ? g_hoff : g_noff;
    int *fill = isH ? g_hfill : g_nfill;
    int n     = isH ? N_HEDGES : N_NODES;
    int start = isH ? 0 : NBH;
    int chunk = isH ? b : b - NBH;
    int t = threadIdx.x;

    // base = sum_{i in [start, b)} g_part[i]
    int contrib = (t < NBT && t >= start && t < b) ? g_part[t] : 0;
#pragma unroll
    for (int o = 16; o > 0; o >>= 1)
        contrib += __shfl_down_sync(0xffffffffu, contrib, o);
    if ((t & 31) == 0) red[t >> 5] = contrib;
    __syncthreads();
    if (t == 0) {
        int acc = 0;
#pragma unroll
        for (int i = 0; i < 32; i++) acc += red[i];
        sbase = acc;
    }
    __syncthreads();

    int i = chunk * 1024 + t;
    int v = (i < n) ? cnt[i] : 0;
    s[t] = v;
    __syncthreads();
    for (int d = 1; d < 1024; d <<= 1) {
        int x = (t >= d) ? s[t - d] : 0;
        __syncthreads();
        s[t] += x;
        __syncthreads();
    }
    int excl = s[t] - v + sbase;
    if (i < n) {
        off[i] = excl;
        fill[i] = excl;
        if (i == n - 1) off[n] = excl + v;
    }
}

__global__ void fill_kernel(const int *__restrict__ node_idx,
                            const int *__restrict__ hedge_idx) {
    int e = blockIdx.x * blockDim.x + threadIdx.x;
    if (e < E_INC) {
        int nd = node_idx[e], he = hedge_idx[e];
        int p = atomicAdd(&g_hfill[he], 1);
        g_csr_h[p] = nd;
        int p2 = atomicAdd(&g_nfill[nd], 1);
        g_csr_n[p2] = he;
        // re-zero counts for the next replay (scans already consumed them)
        if (e < N_HEDGES) g_hcnt[e] = 0;
        if (e < N_NODES)  g_ncnt[e] = 0;
    }
}

// ---------------- embed: h = x @ W_embed + b ----------------
#define WT_PITCH 100
__global__ void __launch_bounds__(256) embed_kernel(
    const float *__restrict__ x, const float *__restrict__ W,
    const float *__restrict__ b, float *__restrict__ h) {
    __shared__ float W_t[H_DIM * WT_PITCH];   // transposed [col][k], 25.6 KB
    __shared__ float x_s[4][IN_DIM];          // 92*4 floats, rows 16B-aligned
    for (int i = threadIdx.x; i < IN_DIM * H_DIM; i += 256) {
        int k = i >> 6, c = i & 63;
        W_t[c * WT_PITCH + k] = W[i];
    }
    int col = threadIdx.x & 63, sub = threadIdx.x >> 6;
    float bv = b[col];
    const float4 *wv = (const float4 *)(W_t + col * WT_PITCH);
    for (int nb = blockIdx.x * 4; nb < N_NODES; nb += gridDim.x * 4) {
        __syncthreads();
        for (int i = threadIdx.x; i < 4 * IN_DIM; i += 256) {
            int n = i / IN_DIM, k = i - n * IN_DIM;
            int node = nb + n;
            x_s[n][k] = (node < N_NODES) ? x[node * IN_DIM + k] : 0.f;
        }
        __syncthreads();
        int node = nb + sub;
        if (node < N_NODES) {
            float acc = bv;
            const float4 *xv = (const float4 *)(x_s[sub]);
#pragma unroll
            for (int k4 = 0; k4 < IN_DIM / 4; k4++) {
                float4 a = xv[k4];
                float4 w = wv[k4];
                acc += a.x * w.x + a.y * w.y + a.z * w.z + a.w * w.w;
            }
            h[node * H_DIM + col] = acc;
        }
    }
}

// ---------------- hedge aggregation (warp per hyperedge) ----------------
__global__ void __launch_bounds__(256) hedge_agg_kernel(const float *__restrict__ hin) {
    int he = blockIdx.x * 8 + (threadIdx.x >> 5);
    if (he >= N_HEDGES) return;
    int lane = threadIdx.x & 31;
    int beg = g_hoff[he], end = g_hoff[he + 1];
    float2 acc = make_float2(0.f, 0.f);
    int m = beg;
    for (; m + 8 <= end; m += 8) {
        int n0 = g_csr_h[m],     n1 = g_csr_h[m + 1];
        int n2 = g_csr_h[m + 2], n3 = g_csr_h[m + 3];
        int n4 = g_csr_h[m + 4], n5 = g_csr_h[m + 5];
        int n6 = g_csr_h[m + 6], n7 = g_csr_h[m + 7];
        float2 v0 = *(const float2 *)(hin + n0 * H_DIM + lane * 2);
        float2 v1 = *(const float2 *)(hin + n1 * H_DIM + lane * 2);
        float2 v2 = *(const float2 *)(hin + n2 * H_DIM + lane * 2);
        float2 v3 = *(const float2 *)(hin + n3 * H_DIM + lane * 2);
        float2 v4 = *(const float2 *)(hin + n4 * H_DIM + lane * 2);
        float2 v5 = *(const float2 *)(hin + n5 * H_DIM + lane * 2);
        float2 v6 = *(const float2 *)(hin + n6 * H_DIM + lane * 2);
        float2 v7 = *(const float2 *)(hin + n7 * H_DIM + lane * 2);
        acc.x += ((v0.x + v1.x) + (v2.x + v3.x)) + ((v4.x + v5.x) + (v6.x + v7.x));
        acc.y += ((v0.y + v1.y) + (v2.y + v3.y)) + ((v4.y + v5.y) + (v6.y + v7.y));
    }
    for (; m < end; m++) {
        int nd = g_csr_h[m];
        float2 v = *(const float2 *)(hin + nd * H_DIM + lane * 2);
        acc.x += v.x; acc.y += v.y;
    }
    int deg = end - beg;
    float inv = 1.f / (float)(deg > 0 ? deg : 1);
    *(float2 *)(g_hxs + he * H_DIM + lane * 2) = make_float2(acc.x * inv, acc.y * inv);
}

// layer-invariant: per-node mean of incident hedge_attr rows
__global__ void __launch_bounds__(256) attr_agg_kernel(const float *__restrict__ hedge_attr) {
    int nd = blockIdx.x * 8 + (threadIdx.x >> 5);
    if (nd >= N_NODES) return;
    int lane = threadIdx.x & 31;
    int beg = g_noff[nd], end = g_noff[nd + 1];
    float a0 = 0.f, a1 = 0.f;
    for (int m = beg; m < end; m++) {
        int he = g_csr_n[m];
        const float *r = hedge_attr + he * HEDGE_DIM;
        a0 += r[lane];
        if (lane < 3) a1 += r[32 + lane];
    }
    int deg = end - beg;
    float inv = 1.f / (float)(deg > 0 ? deg : 1);
    g_attragg[nd * HEDGE_DIM + lane] = a0 * inv;
    if (lane < 3) g_attragg[nd * HEDGE_DIM + 32 + lane] = a1 * inv;
}

// ---------------- per-layer fused node-agg + dual GEMM + activation -------
// 64 nodes / block, 128 threads. Staging builds z = [h | attragg | nodeagg]
// with the node aggregation (mean of hxs rows) computed INLINE (block-local).
// GEMM: each thread 2 nodes x 32 combined cols; cols 0..63 = Wf, 64..127 = Wc.
#define GEMM_SMEM (64 * Z_DIM * 4 + 32 * 128 * 4)   // 58112 B
__global__ void __launch_bounds__(128) gemm_act_kernel(
    const float *__restrict__ h_in,
    const float *__restrict__ Wf, const float *__restrict__ bf,
    const float *__restrict__ Wc, const float *__restrict__ bc,
    float *__restrict__ h_out) {
    extern __shared__ float sm[];
    float *z_s = sm;                      // [64][Z_DIM]
    float *W_s = sm + 64 * Z_DIM;         // [32][128]
    const int tid = threadIdx.x;
    const int nbase = blockIdx.x * 64;
    const int lane = tid & 31, w = tid >> 5;

    // ---- stage z for this block's 64 nodes; warp w covers nodes [16w,16w+16)
    for (int n = w * 16; n < w * 16 + 16; n++) {
        int node = nbase + n;
        float *zr = z_s + n * Z_DIM;
        int beg = 0, end = 0;
        if (node < N_NODES) { beg = g_noff[node]; end = g_noff[node + 1]; }
        int deg = end - beg;
        // node aggregation over incident hedges (mean of g_hxs rows)
        float2 acc = make_float2(0.f, 0.f);
        int m = beg;
        for (; m + 4 <= end; m += 4) {
            int h0 = g_csr_n[m],     h1 = g_csr_n[m + 1];
            int h2 = g_csr_n[m + 2], h3 = g_csr_n[m + 3];
            float2 v0 = *(const float2 *)(g_hxs + h0 * H_DIM + lane * 2);
            float2 v1 = *(const float2 *)(g_hxs + h1 * H_DIM + lane * 2);
            float2 v2 = *(const float2 *)(g_hxs + h2 * H_DIM + lane * 2);
            float2 v3 = *(const float2 *)(g_hxs + h3 * H_DIM + lane * 2);
            acc.x += (v0.x + v1.x) + (v2.x + v3.x);
            acc.y += (v0.y + v1.y) + (v2.y + v3.y);
        }
        for (; m < end; m++) {
            int he = g_csr_n[m];
            float2 v = *(const float2 *)(g_hxs + he * H_DIM + lane * 2);
            acc.x += v.x; acc.y += v.y;
        }
        float inv = 1.f / (float)(deg > 0 ? deg : 1);
        zr[99 + 2 * lane]  = acc.x * inv;
        zr[100 + 2 * lane] = acc.y * inv;
        // h part (0 if isolated node), attr part
        float2 hv = make_float2(0.f, 0.f);
        float a0 = 0.f, a1 = 0.f;
        if (node < N_NODES) {
            if (deg > 0) hv = *(const float2 *)(h_in + node * H_DIM + lane * 2);
            a0 = g_attragg[node * HEDGE_DIM + lane];
            if (lane < 3) a1 = g_attragg[node * HEDGE_DIM + 32 + lane];
        }
        zr[2 * lane]     = hv.x;
        zr[2 * lane + 1] = hv.y;
        zr[64 + lane] = a0;
        if (lane < 3) zr[96 + lane] = a1;
    }

    // ---- dual GEMM
    const int q = lane & 3, nsub = lane >> 2;
    const int nl0 = w * 8 + nsub;
    const int nl1 = nl0 + 32;

    ull acc0[16], acc1[16];
#pragma unroll
    for (int i = 0; i < 16; i++) { acc0[i] = 0ull; acc1[i] = 0ull; }

    for (int kb = 0; kb < Z_DIM; kb += 32) {
        int kc = (Z_DIM - kb < 32) ? (Z_DIM - kb) : 32;
        __syncthreads();
        for (int idx = tid; idx < kc * 128; idx += 128) {
            int k = idx >> 7, c = idx & 127;
            W_s[k * 128 + c] = (c < 64) ? Wf[(kb + k) * 64 + c]
                                        : Wc[(kb + k) * 64 + (c - 64)];
        }
        __syncthreads();
        for (int k = 0; k < kc; k++) {
            ull a0 = packdup(z_s[nl0 * Z_DIM + kb + k]);
            ull a1 = packdup(z_s[nl1 * Z_DIM + kb + k]);
            const ulonglong2 *wr = (const ulonglong2 *)(W_s + k * 128 + q * 32);
#pragma unroll
            for (int i = 0; i < 8; i++) {
                ulonglong2 wp = wr[i];
                fma2(acc0[2 * i],     a0, wp.x);
                fma2(acc0[2 * i + 1], a0, wp.y);
                fma2(acc1[2 * i],     a1, wp.x);
                fma2(acc1[2 * i + 1], a1, wp.y);
            }
        }
    }

    // ---- epilogue: bias, pair f(q<2) with c(q>=2) via shfl_xor(2), activate
    const float *bias = (q < 2) ? bf : bc;
    const int halfbase = (q & 1) * 32;
#pragma unroll
    for (int which = 0; which < 2; which++) {
        ull *acc = which ? acc1 : acc0;
        int node = nbase + (which ? nl1 : nl0);
#pragma unroll
        for (int i = 0; i < 16; i++) {
            float2 y = unpk(acc[i]);
            int col = halfbase + 2 * i;
            y.x += bias[col];
            y.y += bias[col + 1];
            float ox = __shfl_xor_sync(0xffffffffu, y.x, 2);
            float oy = __shfl_xor_sync(0xffffffffu, y.y, 2);
            if (q < 2 && node < N_NODES) {
                int base = node * H_DIM + col;
                float o0 = sigmoidf(y.x) * softplusf(ox);
                float o1 = sigmoidf(y.y) * softplusf(oy);
                h_out[base]     = softplusf(o0 + h_in[base]);
                h_out[base + 1] = softplusf(o1 + h_in[base + 1]);
            }
        }
    }
}

// ---------------- pooling + readout MLP (block per graph) ----------------
__global__ void __launch_bounds__(128) pool_mlp_kernel(
    const float *__restrict__ h, const int *__restrict__ batch,
    const float *__restrict__ Wp, const float *__restrict__ bp,
    const float *__restrict__ Wo, const float *__restrict__ bo,
    float *__restrict__ out) {
    int g = blockIdx.x;
    int tid = threadIdx.x;
    __shared__ int s_lo, s_hi;
    if (tid == 0) {
        int lo = 0, hi = N_NODES;
        while (lo < hi) { int mid = (lo + hi) >> 1; if (batch[mid] < g) lo = mid + 1; else hi = mid; }
        s_lo = lo;
    }
    if (tid == 1) {
        int lo = 0, hi = N_NODES;
        while (lo < hi) { int mid = (lo + hi) >> 1; if (batch[mid] < g + 1) lo = mid + 1; else hi = mid; }
        s_hi = lo;
    }
    __syncthreads();
    int lo = s_lo, hi = s_hi;
    int col = tid & 63, sub = tid >> 6;
    float acc = 0.f;
    for (int i = lo + sub; i < hi; i += 2) acc += h[i * H_DIM + col];
    __shared__ float gs[2][H_DIM];
    gs[sub][col] = acc;
    __syncthreads();
    __shared__ float gvec[H_DIM];
    if (tid < 64) {
        int cnt = hi - lo;
        gvec[tid] = (gs[0][tid] + gs[1][tid]) / (float)(cnt > 0 ? cnt : 1);
    }
    __syncthreads();
    float p = bp[tid];
#pragma unroll
    for (int k = 0; k < H_DIM; k++) p += gvec[k] * Wp[k * HOUT + tid];
    p = softplusf(p);
    float r = p * Wo[tid];
#pragma unroll
    for (int off = 16; off > 0; off >>= 1) r += __shfl_down_sync(0xffffffffu, r, off);
    __shared__ float red[4];
    if ((tid & 31) == 0) red[tid >> 5] = r;
    __syncthreads();
    if (tid == 0) out[g] = red[0] + red[1] + red[2] + red[3] + bo[0];
}

// ---------------- launch ----------------
// Launch order is chosen so the ncu capture (-s 5 -c 1) lands on
// hedge_agg_kernel (layer 1): count[0] partial[1] final[2] fill[3] embed[4]
// hedge_agg[5] attr[6] gemm[7] ...
extern "C" void kernel_launch(void *const *d_in, const int *in_sizes, int n_in,
                              void *d_out, int out_size) {
    const float *x          = (const float *)d_in[0];
    const float *hedge_attr = (const float *)d_in[1];
    const int   *node_idx   = (const int *)d_in[2];
    const int   *hedge_idx  = (const int *)d_in[3];
    const int   *batch      = (const int *)d_in[4];
    const float *W_embed    = (const float *)d_in[5];
    const float *b_embed    = (const float *)d_in[6];
    const float *Wf         = (const float *)d_in[7];
    const float *bf         = (const float *)d_in[8];
    const float *Wc         = (const float *)d_in[9];
    const float *bc         = (const float *)d_in[10];
    const float *Wp         = (const float *)d_in[11];
    const float *bp         = (const float *)d_in[12];
    const float *Wo         = (const float *)d_in[13];
    const float *bo         = (const float *)d_in[14];
    float *out = (float *)d_out;

    void *p_hA, *p_hB;
    cudaGetSymbolAddress(&p_hA, g_hA);
    cudaGetSymbolAddress(&p_hB, g_hB);
    float *hA = (float *)p_hA;
    float *hB = (float *)p_hB;

    cudaFuncSetAttribute(gemm_act_kernel,
                         cudaFuncAttributeMaxDynamicSharedMemorySize, GEMM_SMEM);

    // CSR build (counts arrive pre-zeroed: BSS init / fill_kernel tail)
    count_kernel<<<(E_INC + 255) / 256, 256>>>(node_idx, hedge_idx);
    scan_partial_both<<<NBT, 1024>>>();
    scan_final_both<<<NBT, 1024>>>();
    fill_kernel<<<(E_INC + 255) / 256, 256>>>(node_idx, hedge_idx);

    // embed
    embed_kernel<<<1184, 256>>>(x, W_embed, b_embed, hA);

    // layers (ping-pong hA/hB); attr_agg (layer-invariant) after hedge_agg L1
    float *hcur = hA, *hnext = hB;
    for (int l = 0; l < N_LAYERS; l++) {
        hedge_agg_kernel<<<(N_HEDGES + 7) / 8, 256>>>(hcur);
        if (l == 0) attr_agg_kernel<<<(N_NODES + 7) / 8, 256>>>(hedge_attr);
        gemm_act_kernel<<<(N_NODES + 63) / 64, 128, GEMM_SMEM>>>(
            hcur,
            Wf + (size_t)l * Z_DIM * H_DIM, bf + (size_t)l * H_DIM,
            Wc + (size_t)l * Z_DIM * H_DIM, bc + (size_t)l * H_DIM,
            hnext);
        float *t = hcur; hcur = hnext; hnext = t;
    }

    // pooling + readout
    pool_mlp_kernel<<<N_GRAPHS, 128>>>(hcur, batch, Wp, bp, Wo, bo, out);
}

// round 9
// speedup vs baseline: 1.0648x; 1.0501x over previous
#include <cuda_runtime.h>
#include <cuda_bf16.h>
#include <math.h>

#define N_NODES   50000
#define N_HEDGES  100000
#define E_INC     800000
#define N_GRAPHS  512
#define IN_DIM    92
#define H_DIM     64
#define HOUT      128
#define HEDGE_DIM 35
#define Z_DIM     163   // 64 + 35 + 64 (logical)
#define Z_PITCH   164   // padded smem row pitch (16B-aligned rows)
#define N_LAYERS  3

#define NBH 98            // ceil(100000/1024)
#define NBN 49            // ceil(50000/1024)
#define NBT (NBH + NBN)   // 147

typedef unsigned long long ull;

// ---------------- scratch (device globals; no allocation allowed) ----------
__device__ float g_hA[N_NODES * H_DIM];
__device__ float g_hB[N_NODES * H_DIM];
__device__ float g_hxs[N_HEDGES * H_DIM];
__device__ float g_attragg[N_NODES * HEDGE_DIM];

__device__ int g_hcnt[N_HEDGES];
__device__ int g_ncnt[N_NODES];
__device__ int g_hoff[N_HEDGES + 1];
__device__ int g_noff[N_NODES + 1];
__device__ int g_hfill[N_HEDGES];
__device__ int g_nfill[N_NODES];
__device__ int g_csr_h[E_INC];   // node ids grouped by hedge
__device__ int g_csr_n[E_INC];   // hedge ids grouped by node
__device__ int g_part[256];

// ---------------- helpers ----------------
__device__ __forceinline__ float softplusf(float x) {
    return fmaxf(x, 0.f) + log1pf(expf(-fabsf(x)));
}
__device__ __forceinline__ float sigmoidf(float x) {
    return 1.f / (1.f + expf(-x));
}
__device__ __forceinline__ ull packdup(float x) {
    ull r;
    asm("mov.b64 %0, {%1, %2};" : "=l"(r)
        : "r"(__float_as_uint(x)), "r"(__float_as_uint(x)));
    return r;
}
__device__ __forceinline__ float2 unpk(ull v) {
    unsigned a, b;
    asm("mov.b64 {%0, %1}, %2;" : "=r"(a), "=r"(b) : "l"(v));
    return make_float2(__uint_as_float(a), __uint_as_float(b));
}
__device__ __forceinline__ void fma2(ull &c, ull a, ull b) {
    asm("fma.rn.f32x2 %0, %1, %2, %0;" : "+l"(c) : "l"(a), "l"(b));
}

// ---------------- CSR construction ----------------
// counts are zeroed by the TAIL of fill_kernel (previous replay / correctness
// run), and are zero at module load. No memsets needed.
__global__ void count_kernel(const int *__restrict__ node_idx,
                             const int *__restrict__ hedge_idx) {
    int e = blockIdx.x * blockDim.x + threadIdx.x;
    if (e < E_INC) {
        atomicAdd(&g_hcnt[hedge_idx[e]], 1);
        atomicAdd(&g_ncnt[node_idx[e]], 1);
    }
}

// one launch: per-chunk sums for BOTH count arrays (blocks 0..NBH-1 = hedges,
// NBH..NBT-1 = nodes)
__global__ void __launch_bounds__(1024) scan_partial_both() {
    __shared__ int s[1024];
    int b = blockIdx.x;
    const int *cnt = (b < NBH) ? g_hcnt : g_ncnt;
    int n = (b < NBH) ? N_HEDGES : N_NODES;
    int chunk = (b < NBH) ? b : b - NBH;
    int i = chunk * 1024 + threadIdx.x;
    s[threadIdx.x] = (i < n) ? cnt[i] : 0;
    __syncthreads();
    for (int d = 512; d > 0; d >>= 1) {
        if (threadIdx.x < d) s[threadIdx.x] += s[threadIdx.x + d];
        __syncthreads();
    }
    if (threadIdx.x == 0) g_part[b] = s[0];
}

// one launch: each block computes its own base = sum of partials in its
// range, then the in-chunk exclusive scan. Writes off + fill.
__global__ void __launch_bounds__(1024) scan_final_both() {
    __shared__ int s[1024];
    __shared__ int red[32];
    __shared__ int sbase;
    int b = blockIdx.x;
    bool isH = b < NBH;
    const int *cnt = isH ? g_hcnt : g_ncnt;
    int *off  = isH ? g_hoff : g_noff;
    int *fill = isH ? g_hfill : g_nfill;
    int n     = isH ? N_HEDGES : N_NODES;
    int start = isH ? 0 : NBH;
    int chunk = isH ? b : b - NBH;
    int t = threadIdx.x;

    // base = sum_{i in [start, b)} g_part[i]
    int contrib = (t < NBT && t >= start && t < b) ? g_part[t] : 0;
#pragma unroll
    for (int o = 16; o > 0; o >>= 1)
        contrib += __shfl_down_sync(0xffffffffu, contrib, o);
    if ((t & 31) == 0) red[t >> 5] = contrib;
    __syncthreads();
    if (t == 0) {
        int acc = 0;
#pragma unroll
        for (int i = 0; i < 32; i++) acc += red[i];
        sbase = acc;
    }
    __syncthreads();

    int i = chunk * 1024 + t;
    int v = (i < n) ? cnt[i] : 0;
    s[t] = v;
    __syncthreads();
    for (int d = 1; d < 1024; d <<= 1) {
        int x = (t >= d) ? s[t - d] : 0;
        __syncthreads();
        s[t] += x;
        __syncthreads();
    }
    int excl = s[t] - v + sbase;
    if (i < n) {
        off[i] = excl;
        fill[i] = excl;
        if (i == n - 1) off[n] = excl + v;
    }
}

__global__ void fill_kernel(const int *__restrict__ node_idx,
                            const int *__restrict__ hedge_idx) {
    int e = blockIdx.x * blockDim.x + threadIdx.x;
    if (e < E_INC) {
        int nd = node_idx[e], he = hedge_idx[e];
        int p = atomicAdd(&g_hfill[he], 1);
        g_csr_h[p] = nd;
        int p2 = atomicAdd(&g_nfill[nd], 1);
        g_csr_n[p2] = he;
        // re-zero counts for the next replay (scans already consumed them)
        if (e < N_HEDGES) g_hcnt[e] = 0;
        if (e < N_NODES)  g_ncnt[e] = 0;
    }
}

// ---------------- embed: h = x @ W_embed + b ----------------
#define WT_PITCH 100
__global__ void __launch_bounds__(256) embed_kernel(
    const float *__restrict__ x, const float *__restrict__ W,
    const float *__restrict__ b, float *__restrict__ h) {
    __shared__ float W_t[H_DIM * WT_PITCH];   // transposed [col][k], 25.6 KB
    __shared__ float x_s[4][IN_DIM];          // 92*4 floats, rows 16B-aligned
    for (int i = threadIdx.x; i < IN_DIM * H_DIM; i += 256) {
        int k = i >> 6, c = i & 63;
        W_t[c * WT_PITCH + k] = W[i];
    }
    int col = threadIdx.x & 63, sub = threadIdx.x >> 6;
    float bv = b[col];
    const float4 *wv = (const float4 *)(W_t + col * WT_PITCH);
    for (int nb = blockIdx.x * 4; nb < N_NODES; nb += gridDim.x * 4) {
        __syncthreads();
        for (int i = threadIdx.x; i < 4 * IN_DIM; i += 256) {
            int n = i / IN_DIM, k = i - n * IN_DIM;
            int node = nb + n;
            x_s[n][k] = (node < N_NODES) ? x[node * IN_DIM + k] : 0.f;
        }
        __syncthreads();
        int node = nb + sub;
        if (node < N_NODES) {
            float acc = bv;
            const float4 *xv = (const float4 *)(x_s[sub]);
#pragma unroll
            for (int k4 = 0; k4 < IN_DIM / 4; k4++) {
                float4 a = xv[k4];
                float4 w = wv[k4];
                acc += a.x * w.x + a.y * w.y + a.z * w.z + a.w * w.w;
            }
            h[node * H_DIM + col] = acc;
        }
    }
}

// ---------------- hedge aggregation (HALF-WARP per hyperedge, float4) -----
// 16 lanes x float4 = one 256B row per gather; 2 independent chains per warp.
__global__ void __launch_bounds__(256) hedge_agg_kernel(const float *__restrict__ hin) {
    int he = blockIdx.x * 16 + (threadIdx.x >> 4);
    if (he >= N_HEDGES) return;
    int l16 = threadIdx.x & 15;
    int beg = g_hoff[he], end = g_hoff[he + 1];
    float4 acc = make_float4(0.f, 0.f, 0.f, 0.f);
    int m = beg;
    for (; m + 4 <= end; m += 4) {
        int n0 = g_csr_h[m],     n1 = g_csr_h[m + 1];
        int n2 = g_csr_h[m + 2], n3 = g_csr_h[m + 3];
        float4 v0 = *(const float4 *)(hin + n0 * H_DIM + l16 * 4);
        float4 v1 = *(const float4 *)(hin + n1 * H_DIM + l16 * 4);
        float4 v2 = *(const float4 *)(hin + n2 * H_DIM + l16 * 4);
        float4 v3 = *(const float4 *)(hin + n3 * H_DIM + l16 * 4);
        acc.x += (v0.x + v1.x) + (v2.x + v3.x);
        acc.y += (v0.y + v1.y) + (v2.y + v3.y);
        acc.z += (v0.z + v1.z) + (v2.z + v3.z);
        acc.w += (v0.w + v1.w) + (v2.w + v3.w);
    }
    for (; m < end; m++) {
        int nd = g_csr_h[m];
        float4 v = *(const float4 *)(hin + nd * H_DIM + l16 * 4);
        acc.x += v.x; acc.y += v.y; acc.z += v.z; acc.w += v.w;
    }
    int deg = end - beg;
    float inv = 1.f / (float)(deg > 0 ? deg : 1);
    *(float4 *)(g_hxs + he * H_DIM + l16 * 4) =
        make_float4(acc.x * inv, acc.y * inv, acc.z * inv, acc.w * inv);
}

// layer-invariant: per-node mean of incident hedge_attr rows
__global__ void __launch_bounds__(256) attr_agg_kernel(const float *__restrict__ hedge_attr) {
    int nd = blockIdx.x * 8 + (threadIdx.x >> 5);
    if (nd >= N_NODES) return;
    int lane = threadIdx.x & 31;
    int beg = g_noff[nd], end = g_noff[nd + 1];
    float a0 = 0.f, a1 = 0.f;
    for (int m = beg; m < end; m++) {
        int he = g_csr_n[m];
        const float *r = hedge_attr + he * HEDGE_DIM;
        a0 += r[lane];
        if (lane < 3) a1 += r[32 + lane];
    }
    int deg = end - beg;
    float inv = 1.f / (float)(deg > 0 ? deg : 1);
    g_attragg[nd * HEDGE_DIM + lane] = a0 * inv;
    if (lane < 3) g_attragg[nd * HEDGE_DIM + 32 + lane] = a1 * inv;
}

// ---------------- per-layer fused node-agg + dual GEMM + activation -------
// 64 nodes / block, 128 threads. Staging: HALF-WARP per node, float4 gathers,
// 2 concurrent chains per warp. z_s rows padded to Z_PITCH=164 so row bases
// are 16B-aligned (misaligned-address fix). GEMM: each thread 2 nodes x 32
// combined cols; cols 0..63 = Wf, 64..127 = Wc.
#define GEMM_SMEM (64 * Z_PITCH * 4 + 32 * 128 * 4)   // 58368 B
__global__ void __launch_bounds__(128) gemm_act_kernel(
    const float *__restrict__ h_in,
    const float *__restrict__ Wf, const float *__restrict__ bf,
    const float *__restrict__ Wc, const float *__restrict__ bc,
    float *__restrict__ h_out) {
    extern __shared__ float sm[];
    float *z_s = sm;                      // [64][Z_PITCH]
    float *W_s = sm + 64 * Z_PITCH;       // [32][128]
    const int tid = threadIdx.x;
    const int nbase = blockIdx.x * 64;
    const int lane = tid & 31, w = tid >> 5;
    const int hw = lane >> 4, l16 = lane & 15;

    // ---- stage z; half-warp (hw) of warp w covers 8 nodes serially
    for (int i = 0; i < 8; i++) {
        int n = w * 16 + hw * 8 + i;
        int node = nbase + n;
        float *zr = z_s + n * Z_PITCH;    // 16B-aligned row base
        int beg = 0, end = 0;
        if (node < N_NODES) { beg = g_noff[node]; end = g_noff[node + 1]; }
        int deg = end - beg;
        // node aggregation over incident hedges (mean of g_hxs rows)
        float4 acc = make_float4(0.f, 0.f, 0.f, 0.f);
        int m = beg;
        for (; m + 4 <= end; m += 4) {
            int h0 = g_csr_n[m],     h1 = g_csr_n[m + 1];
            int h2 = g_csr_n[m + 2], h3 = g_csr_n[m + 3];
            float4 v0 = *(const float4 *)(g_hxs + h0 * H_DIM + l16 * 4);
            float4 v1 = *(const float4 *)(g_hxs + h1 * H_DIM + l16 * 4);
            float4 v2 = *(const float4 *)(g_hxs + h2 * H_DIM + l16 * 4);
            float4 v3 = *(const float4 *)(g_hxs + h3 * H_DIM + l16 * 4);
            acc.x += (v0.x + v1.x) + (v2.x + v3.x);
            acc.y += (v0.y + v1.y) + (v2.y + v3.y);
            acc.z += (v0.z + v1.z) + (v2.z + v3.z);
            acc.w += (v0.w + v1.w) + (v2.w + v3.w);
        }
        for (; m < end; m++) {
            int he = g_csr_n[m];
            float4 v = *(const float4 *)(g_hxs + he * H_DIM + l16 * 4);
            acc.x += v.x; acc.y += v.y; acc.z += v.z; acc.w += v.w;
        }
        float inv = 1.f / (float)(deg > 0 ? deg : 1);
        // nodeagg at z[99..162] (odd base -> scalar stores)
        zr[99 + l16 * 4]     = acc.x * inv;
        zr[99 + l16 * 4 + 1] = acc.y * inv;
        zr[99 + l16 * 4 + 2] = acc.z * inv;
        zr[99 + l16 * 4 + 3] = acc.w * inv;
        // h part (0 if isolated node) at z[0..63]
        float4 hv = make_float4(0.f, 0.f, 0.f, 0.f);
        float a0 = 0.f, a1 = 0.f, a2 = 0.f;
        if (node < N_NODES) {
            if (deg > 0) hv = *(const float4 *)(h_in + node * H_DIM + l16 * 4);
            a0 = g_attragg[node * HEDGE_DIM + l16];
            a1 = g_attragg[node * HEDGE_DIM + 16 + l16];
            if (l16 < 3) a2 = g_attragg[node * HEDGE_DIM + 32 + l16];
        }
        *(float4 *)(zr + l16 * 4) = hv;   // aligned: row base 16B, +16B steps
        // attr part at z[64..98]
        zr[64 + l16] = a0;
        zr[80 + l16] = a1;
        if (l16 < 3) zr[96 + l16] = a2;
    }

    // ---- dual GEMM
    const int q = lane & 3, nsub = lane >> 2;
    const int nl0 = w * 8 + nsub;
    const int nl1 = nl0 + 32;

    ull acc0[16], acc1[16];
#pragma unroll
    for (int i = 0; i < 16; i++) { acc0[i] = 0ull; acc1[i] = 0ull; }

    for (int kb = 0; kb < Z_DIM; kb += 32) {
        int kc = (Z_DIM - kb < 32) ? (Z_DIM - kb) : 32;
        __syncthreads();
        for (int idx = tid; idx < kc * 128; idx += 128) {
            int k = idx >> 7, c = idx & 127;
            W_s[k * 128 + c] = (c < 64) ? Wf[(kb + k) * 64 + c]
                                        : Wc[(kb + k) * 64 + (c - 64)];
        }
        __syncthreads();
        for (int k = 0; k < kc; k++) {
            ull a0 = packdup(z_s[nl0 * Z_PITCH + kb + k]);
            ull a1 = packdup(z_s[nl1 * Z_PITCH + kb + k]);
            const ulonglong2 *wr = (const ulonglong2 *)(W_s + k * 128 + q * 32);
#pragma unroll
            for (int i = 0; i < 8; i++) {
                ulonglong2 wp = wr[i];
                fma2(acc0[2 * i],     a0, wp.x);
                fma2(acc0[2 * i + 1], a0, wp.y);
                fma2(acc1[2 * i],     a1, wp.x);
                fma2(acc1[2 * i + 1], a1, wp.y);
            }
        }
    }

    // ---- epilogue: bias, pair f(q<2) with c(q>=2) via shfl_xor(2), activate
    const float *bias = (q < 2) ? bf : bc;
    const int halfbase = (q & 1) * 32;
#pragma unroll
    for (int which = 0; which < 2; which++) {
        ull *acc = which ? acc1 : acc0;
        int node = nbase + (which ? nl1 : nl0);
#pragma unroll
        for (int i = 0; i < 16; i++) {
            float2 y = unpk(acc[i]);
            int col = halfbase + 2 * i;
            y.x += bias[col];
            y.y += bias[col + 1];
            float ox = __shfl_xor_sync(0xffffffffu, y.x, 2);
            float oy = __shfl_xor_sync(0xffffffffu, y.y, 2);
            if (q < 2 && node < N_NODES) {
                int base = node * H_DIM + col;
                float o0 = sigmoidf(y.x) * softplusf(ox);
                float o1 = sigmoidf(y.y) * softplusf(oy);
                h_out[base]     = softplusf(o0 + h_in[base]);
                h_out[base + 1] = softplusf(o1 + h_in[base + 1]);
            }
        }
    }
}

// ---------------- pooling + readout MLP (block per graph) ----------------
__global__ void __launch_bounds__(128) pool_mlp_kernel(
    const float *__restrict__ h, const int *__restrict__ batch,
    const float *__restrict__ Wp, const float *__restrict__ bp,
    const float *__restrict__ Wo, const float *__restrict__ bo,
    float *__restrict__ out) {
    int g = blockIdx.x;
    int tid = threadIdx.x;
    __shared__ int s_lo, s_hi;
    if (tid == 0) {
        int lo = 0, hi = N_NODES;
        while (lo < hi) { int mid = (lo + hi) >> 1; if (batch[mid] < g) lo = mid + 1; else hi = mid; }
        s_lo = lo;
    }
    if (tid == 1) {
        int lo = 0, hi = N_NODES;
        while (lo < hi) { int mid = (lo + hi) >> 1; if (batch[mid] < g + 1) lo = mid + 1; else hi = mid; }
        s_hi = lo;
    }
    __syncthreads();
    int lo = s_lo, hi = s_hi;
    int col = tid & 63, sub = tid >> 6;
    float acc = 0.f;
    for (int i = lo + sub; i < hi; i += 2) acc += h[i * H_DIM + col];
    __shared__ float gs[2][H_DIM];
    gs[sub][col] = acc;
    __syncthreads();
    __shared__ float gvec[H_DIM];
    if (tid < 64) {
        int cnt = hi - lo;
        gvec[tid] = (gs[0][tid] + gs[1][tid]) / (float)(cnt > 0 ? cnt : 1);
    }
    __syncthreads();
    float p = bp[tid];
#pragma unroll
    for (int k = 0; k < H_DIM; k++) p += gvec[k] * Wp[k * HOUT + tid];
    p = softplusf(p);
    float r = p * Wo[tid];
#pragma unroll
    for (int off = 16; off > 0; off >>= 1) r += __shfl_down_sync(0xffffffffu, r, off);
    __shared__ float red[4];
    if ((tid & 31) == 0) red[tid >> 5] = r;
    __syncthreads();
    if (tid == 0) out[g] = red[0] + red[1] + red[2] + red[3] + bo[0];
}

// ---------------- launch ----------------
// embed placed at capture index 3 (the slot ncu empirically profiles) so this
// round's profile covers a previously-unmeasured kernel.
extern "C" void kernel_launch(void *const *d_in, const int *in_sizes, int n_in,
                              void *d_out, int out_size) {
    const float *x          = (const float *)d_in[0];
    const float *hedge_attr = (const float *)d_in[1];
    const int   *node_idx   = (const int *)d_in[2];
    const int   *hedge_idx  = (const int *)d_in[3];
    const int   *batch      = (const int *)d_in[4];
    const float *W_embed    = (const float *)d_in[5];
    const float *b_embed    = (const float *)d_in[6];
    const float *Wf         = (const float *)d_in[7];
    const float *bf         = (const float *)d_in[8];
    const float *Wc         = (const float *)d_in[9];
    const float *bc         = (const float *)d_in[10];
    const float *Wp         = (const float *)d_in[11];
    const float *bp         = (const float *)d_in[12];
    const float *Wo         = (const float *)d_in[13];
    const float *bo         = (const float *)d_in[14];
    float *out = (float *)d_out;

    void *p_hA, *p_hB;
    cudaGetSymbolAddress(&p_hA, g_hA);
    cudaGetSymbolAddress(&p_hB, g_hB);
    float *hA = (float *)p_hA;
    float *hB = (float *)p_hB;

    cudaFuncSetAttribute(gemm_act_kernel,
                         cudaFuncAttributeMaxDynamicSharedMemorySize, GEMM_SMEM);

    // CSR build (counts arrive pre-zeroed: BSS init / fill_kernel tail)
    count_kernel<<<(E_INC + 255) / 256, 256>>>(node_idx, hedge_idx);       // 0
    scan_partial_both<<<NBT, 1024>>>();                                     // 1
    scan_final_both<<<NBT, 1024>>>();                                       // 2
    embed_kernel<<<1184, 256>>>(x, W_embed, b_embed, hA);                   // 3 (profiled)
    fill_kernel<<<(E_INC + 255) / 256, 256>>>(node_idx, hedge_idx);         // 4

    // layers (ping-pong hA/hB); attr_agg (layer-invariant) inside layer 0
    float *hcur = hA, *hnext = hB;
    for (int l = 0; l < N_LAYERS; l++) {
        hedge_agg_kernel<<<(N_HEDGES + 15) / 16, 256>>>(hcur);
        if (l == 0) attr_agg_kernel<<<(N_NODES + 7) / 8, 256>>>(hedge_attr);
        gemm_act_kernel<<<(N_NODES + 63) / 64, 128, GEMM_SMEM>>>(
            hcur,
            Wf + (size_t)l * Z_DIM * H_DIM, bf + (size_t)l * H_DIM,
            Wc + (size_t)l * Z_DIM * H_DIM, bc + (size_t)l * H_DIM,
            hnext);
        float *t = hcur; hcur = hnext; hnext = t;
    }

    // pooling + readout
    pool_mlp_kernel<<<N_GRAPHS, 128>>>(hcur, batch, Wp, bp, Wo, bo, out);
}